// round 13
// baseline (speedup 1.0000x reference)
#include <cuda_runtime.h>
#include <cuda_bf16.h>
#include <cstdint>

#define CH    128
#define NREL  8
#define MAXN  100000
#define MAXE  1600000
#define RNMAX (NREL * MAXN)
#define CHUNK 4096
#define NCHUNKS ((RNMAX + CHUNK - 1) / CHUNK)

// Static scratch (CSR only now; g_xw eliminated)
__device__ int g_cnt[RNMAX];
__device__ int g_start[RNMAX + 1];
__device__ int g_pos[RNMAX];
__device__ int g_sorted[MAXE];
__device__ int g_blocksum[NCHUNKS];

// ---------------- CSR build ----------------
__global__ void zero_cnt_kernel(int n) {
    int i = blockIdx.x * blockDim.x + threadIdx.x;
    if (i < n) g_cnt[i] = 0;
}

__global__ void hist_kernel(const int* __restrict__ ei,
                            const int* __restrict__ et, int E, int N) {
    int e = blockIdx.x * blockDim.x + threadIdx.x;
    if (e >= E) return;
    int dst = ei[E + e];
    int t   = et[e];
    int src = ei[e];
    if ((unsigned)dst >= (unsigned)N || (unsigned)t >= NREL ||
        (unsigned)src >= (unsigned)N) return;
    atomicAdd(&g_cnt[t * N + dst], 1);
}

__global__ void scan_blocksum_kernel(int n) {
    __shared__ int sdata[256];
    int b = blockIdx.x, t = threadIdx.x;
    int base = b * CHUNK;
    int sum = 0;
    for (int i = t; i < CHUNK; i += 256) {
        int idx = base + i;
        sum += (idx < n) ? g_cnt[idx] : 0;
    }
    sdata[t] = sum;
    __syncthreads();
    for (int s = 128; s > 0; s >>= 1) {
        if (t < s) sdata[t] += sdata[t + s];
        __syncthreads();
    }
    if (t == 0) g_blocksum[b] = sdata[0];
}

__global__ void scan_offsets_kernel(int nb, int n) {
    if (threadIdx.x == 0 && blockIdx.x == 0) {
        int acc = 0;
        for (int i = 0; i < nb; i++) {
            int v = g_blocksum[i];
            g_blocksum[i] = acc;
            acc += v;
        }
        g_start[n] = acc;
    }
}

__global__ void scan_chunk_kernel(int n) {
    __shared__ int sdata[256];
    int b = blockIdx.x, t = threadIdx.x;
    int base = b * CHUNK + t * 16;
    int local[16];
    int sum = 0;
#pragma unroll
    for (int i = 0; i < 16; i++) {
        int idx = base + i;
        int v = (idx < n) ? g_cnt[idx] : 0;
        local[i] = sum;
        sum += v;
    }
    sdata[t] = sum;
    __syncthreads();
    if (t == 0) {
        int acc = 0;
        for (int i = 0; i < 256; i++) { int v = sdata[i]; sdata[i] = acc; acc += v; }
    }
    __syncthreads();
    int off = g_blocksum[b] + sdata[t];
#pragma unroll
    for (int i = 0; i < 16; i++) {
        int idx = base + i;
        if (idx < n) {
            int v = off + local[i];
            g_start[idx] = v;
            g_pos[idx]   = v;
        }
    }
}

__global__ void scatter_edges_kernel(const int* __restrict__ ei,
                                     const int* __restrict__ et, int E, int N) {
    int e = blockIdx.x * blockDim.x + threadIdx.x;
    if (e >= E) return;
    int src = ei[e];
    int dst = ei[E + e];
    int t   = et[e];
    if ((unsigned)dst >= (unsigned)N || (unsigned)t >= NREL ||
        (unsigned)src >= (unsigned)N) return;
    int pos = atomicAdd(&g_pos[t * N + dst], 1);
    g_sorted[pos] = src;
}

// ---------------- fused gather + tensor GEMM ----------------
// out[N,128] = A[N,1152] @ Bcat[1152,128] + bias, where A is built on the fly:
//   k-tile kt<32 : relation r=kt>>2, A rows = mean over CSR segment of x slices
//   k-tile 32..35: A rows = x rows (root slot)
// bf16 2-term split (hi/lo): out = Ah*Bh + Ah*Bl + Al*Bh  (fp32 accum, mma.sync)
#define AS_STRIDE 40    // halves per A smem row (pad 32->40)
#define BS_STRIDE 136   // halves per B smem row (pad 128->136)

__device__ __forceinline__ uint32_t smem_u32(const void* p) {
    uint32_t a;
    asm("{ .reg .u64 t; cvta.to.shared.u64 t, %1; cvt.u32.u64 %0, t; }"
        : "=r"(a) : "l"(p));
    return a;
}

__device__ __forceinline__ void split2(float v0, float v1,
                                       uint32_t& hi, uint32_t& lo) {
    __nv_bfloat16 h0 = __float2bfloat16(v0);
    __nv_bfloat16 h1 = __float2bfloat16(v1);
    __nv_bfloat16 l0 = __float2bfloat16(v0 - __bfloat162float(h0));
    __nv_bfloat16 l1 = __float2bfloat16(v1 - __bfloat162float(h1));
    hi = (uint32_t)__bfloat16_as_ushort(h0) | ((uint32_t)__bfloat16_as_ushort(h1) << 16);
    lo = (uint32_t)__bfloat16_as_ushort(l0) | ((uint32_t)__bfloat16_as_ushort(l1) << 16);
}

#define LDSM_X4(r, addr)                                                        \
    asm volatile("ldmatrix.sync.aligned.m8n8.x4.shared.b16 {%0,%1,%2,%3},[%4];" \
                 : "=r"((r)[0]), "=r"((r)[1]), "=r"((r)[2]), "=r"((r)[3])        \
                 : "r"(addr))
#define LDSM_X4T(r, addr)                                                             \
    asm volatile("ldmatrix.sync.aligned.m8n8.x4.trans.shared.b16 {%0,%1,%2,%3},[%4];" \
                 : "=r"((r)[0]), "=r"((r)[1]), "=r"((r)[2]), "=r"((r)[3])              \
                 : "r"(addr))
#define MMA_BF16(d, a, b0, b1)                                              \
    asm volatile("mma.sync.aligned.m16n8k16.row.col.f32.bf16.bf16.f32 "     \
                 "{%0,%1,%2,%3},{%4,%5,%6,%7},{%8,%9},{%0,%1,%2,%3};"       \
                 : "+f"((d)[0]), "+f"((d)[1]), "+f"((d)[2]), "+f"((d)[3])    \
                 : "r"((a)[0]), "r"((a)[1]), "r"((a)[2]), "r"((a)[3]),       \
                   "r"(b0), "r"(b1))

__global__ __launch_bounds__(256) void gemm_kernel(
    const float* __restrict__ x,
    const float* __restrict__ weight, const float* __restrict__ root,
    const float* __restrict__ bias, float* __restrict__ out, int N) {
    __shared__ __align__(16) unsigned short AsH[128 * AS_STRIDE];
    __shared__ __align__(16) unsigned short AsL[128 * AS_STRIDE];
    __shared__ __align__(16) unsigned short BsH[32 * BS_STRIDE];
    __shared__ __align__(16) unsigned short BsL[32 * BS_STRIDE];

    const int tid  = threadIdx.x;
    const int lane = tid & 31;
    const int wid  = tid >> 5;
    const int m0   = blockIdx.x * 128;
    const int wm   = (wid >> 1) * 32;   // warp m-offset
    const int wn   = (wid & 1) * 64;    // warp n-offset

    const float4* x4 = (const float4*)x;   // x row stride = 32 float4

    // A staging assignment: 2 threads per row, each half-row = 4 float4 (64B)
    const int arow  = tid >> 1;
    const int ahalf = tid & 1;
    const int agr   = m0 + arow;

    float acc[2][8][4];
#pragma unroll
    for (int i = 0; i < 2; i++)
#pragma unroll
        for (int j = 0; j < 8; j++)
#pragma unroll
            for (int q = 0; q < 4; q++) acc[i][j][q] = 0.0f;

    for (int kt = 0; kt < 36; ++kt) {
        const int q0 = (kt & 3) * 8 + ahalf * 4;   // float4 offset within x row

        // --- stage A: gather/mean (kt<32) or direct x (kt>=32) ---
        float4 v[4];
#pragma unroll
        for (int j = 0; j < 4; j++) v[j] = make_float4(0.f, 0.f, 0.f, 0.f);
        if (agr < N) {
            if (kt < 32) {
                int r   = kt >> 2;
                int seg = r * N + agr;
                int b   = g_start[seg];
                int e2  = g_start[seg + 1];
                for (int e = b; e < e2; e++) {
                    int src = g_sorted[e];
                    const float4* xr = x4 + (size_t)src * 32 + q0;
#pragma unroll
                    for (int j = 0; j < 4; j++) {
                        float4 t = xr[j];
                        v[j].x += t.x; v[j].y += t.y; v[j].z += t.z; v[j].w += t.w;
                    }
                }
                if (e2 > b) {
                    float inv = 1.0f / (float)(e2 - b);
#pragma unroll
                    for (int j = 0; j < 4; j++) {
                        v[j].x *= inv; v[j].y *= inv; v[j].z *= inv; v[j].w *= inv;
                    }
                }
            } else {
                const float4* xr = x4 + (size_t)agr * 32 + q0;
#pragma unroll
                for (int j = 0; j < 4; j++) v[j] = xr[j];
            }
        }
        {
            int o = arow * AS_STRIDE + ahalf * 16;
#pragma unroll
            for (int j = 0; j < 4; j++) {
                uint32_t h0, l0, h1, l1;
                split2(v[j].x, v[j].y, h0, l0);
                split2(v[j].z, v[j].w, h1, l1);
                *(uint32_t*)&AsH[o + j * 4]     = h0;
                *(uint32_t*)&AsH[o + j * 4 + 2] = h1;
                *(uint32_t*)&AsL[o + j * 4]     = l0;
                *(uint32_t*)&AsL[o + j * 4 + 2] = l1;
            }
        }

        // --- stage B: [32 k x 128 n] fp32 -> split bf16 hi/lo ---
        const float4* Bsrc = (kt < 32)
            ? (const float4*)(weight + (size_t)kt * 32 * 128)
            : (const float4*)(root + (size_t)(kt - 32) * 32 * 128);
#pragma unroll
        for (int it = 0; it < 4; ++it) {
            int f    = tid + it * 256;    // 0..1023
            int krow = f >> 5;
            int n4   = f & 31;
            float4 w = Bsrc[f];
            uint32_t h0, l0, h1, l1;
            split2(w.x, w.y, h0, l0);
            split2(w.z, w.w, h1, l1);
            int o = krow * BS_STRIDE + n4 * 4;
            *(uint32_t*)&BsH[o]     = h0;
            *(uint32_t*)&BsH[o + 2] = h1;
            *(uint32_t*)&BsL[o]     = l0;
            *(uint32_t*)&BsL[o + 2] = l1;
        }
        __syncthreads();

#pragma unroll
        for (int kk = 0; kk < 32; kk += 16) {
            uint32_t ah[2][4], al[2][4];
#pragma unroll
            for (int mi = 0; mi < 2; mi++) {
                int r = wm + mi * 16 + (lane & 15);
                int c = kk + (lane >> 4) * 8;
                LDSM_X4(ah[mi], smem_u32(&AsH[r * AS_STRIDE + c]));
                LDSM_X4(al[mi], smem_u32(&AsL[r * AS_STRIDE + c]));
            }
            uint32_t bh[4][4], bl[4][4];
#pragma unroll
            for (int ni = 0; ni < 4; ni++) {
                int r = kk + (lane & 15);
                int c = wn + ni * 16 + (lane >> 4) * 8;
                LDSM_X4T(bh[ni], smem_u32(&BsH[r * BS_STRIDE + c]));
                LDSM_X4T(bl[ni], smem_u32(&BsL[r * BS_STRIDE + c]));
            }
#pragma unroll
            for (int mi = 0; mi < 2; mi++)
#pragma unroll
                for (int ni = 0; ni < 4; ni++) {
                    MMA_BF16(acc[mi][ni * 2],     ah[mi], bh[ni][0], bh[ni][1]);
                    MMA_BF16(acc[mi][ni * 2],     ah[mi], bl[ni][0], bl[ni][1]);
                    MMA_BF16(acc[mi][ni * 2],     al[mi], bh[ni][0], bh[ni][1]);
                    MMA_BF16(acc[mi][ni * 2 + 1], ah[mi], bh[ni][2], bh[ni][3]);
                    MMA_BF16(acc[mi][ni * 2 + 1], ah[mi], bl[ni][2], bl[ni][3]);
                    MMA_BF16(acc[mi][ni * 2 + 1], al[mi], bh[ni][2], bh[ni][3]);
                }
        }
        __syncthreads();
    }

    // epilogue
    int r0 = lane >> 2;
    int c0 = (lane & 3) * 2;
#pragma unroll
    for (int mi = 0; mi < 2; mi++)
#pragma unroll
        for (int n8 = 0; n8 < 8; n8++) {
            int gn = wn + n8 * 8 + c0;
            float b0 = bias[gn], b1 = bias[gn + 1];
            int gm = m0 + wm + mi * 16 + r0;
            if (gm < N) {
                float2* p = (float2*)(out + (size_t)gm * CH + gn);
                *p = make_float2(acc[mi][n8][0] + b0, acc[mi][n8][1] + b1);
            }
            if (gm + 8 < N) {
                float2* p = (float2*)(out + (size_t)(gm + 8) * CH + gn);
                *p = make_float2(acc[mi][n8][2] + b0, acc[mi][n8][3] + b1);
            }
        }
}

// ---------------- launch ----------------
extern "C" void kernel_launch(void* const* d_in, const int* in_sizes, int n_in,
                              void* d_out, int out_size) {
    const float* x      = (const float*)d_in[0];
    const int*   ei     = (const int*)d_in[1];    // int32 (JAX x64 off)
    const int*   et     = (const int*)d_in[2];
    const float* weight = (const float*)d_in[3];
    const float* root   = (const float*)d_in[4];
    const float* bias   = (const float*)d_in[5];
    float*       out    = (float*)d_out;

    int N  = in_sizes[0] / CH;       // 100000
    int E  = in_sizes[2];            // 1600000
    int RN = NREL * N;
    int nb = (RN + CHUNK - 1) / CHUNK;
    int gemm_blocks = (N + 127) / 128;

    // CSR build
    zero_cnt_kernel<<<(RN + 255) / 256, 256>>>(RN);
    hist_kernel<<<(E + 255) / 256, 256>>>(ei, et, E, N);
    scan_blocksum_kernel<<<nb, 256>>>(RN);
    scan_offsets_kernel<<<1, 32>>>(nb, RN);
    scan_chunk_kernel<<<nb, 256>>>(RN);
    scatter_edges_kernel<<<(E + 255) / 256, 256>>>(ei, et, E, N);

    // fused gather + GEMM: out = [h_0..h_7 | x] @ [W_0..W_7; root] + bias
    gemm_kernel<<<gemm_blocks, 256>>>(x, weight, root, bias, out, N);
}

// round 17
// speedup vs baseline: 1.0155x; 1.0155x over previous
#include <cuda_runtime.h>
#include <cuda_bf16.h>
#include <cstdint>

#define CH    128
#define NREL  8
#define MAXN  100000
#define MAXE  1600000
#define RNMAX (NREL * MAXN)
#define CHUNK 4096
#define NCHUNKS ((RNMAX + CHUNK - 1) / CHUNK)

// Static scratch: A matrix [slot][node][128] (410MB) + CSR
__device__ __align__(16) float g_xw[(size_t)RNMAX * CH];
__device__ int g_cnt[RNMAX];
__device__ int g_start[RNMAX + 1];
__device__ int g_pos[RNMAX];
__device__ int g_sorted[MAXE];
__device__ int g_blocksum[NCHUNKS];

// ---------------- CSR build ----------------
__global__ void zero_cnt_kernel(int n) {
    int i = blockIdx.x * blockDim.x + threadIdx.x;
    if (i < n) g_cnt[i] = 0;
}

__global__ void hist_kernel(const int* __restrict__ ei,
                            const int* __restrict__ et, int E, int N) {
    int e = blockIdx.x * blockDim.x + threadIdx.x;
    if (e >= E) return;
    int dst = ei[E + e];
    int t   = et[e];
    int src = ei[e];
    if ((unsigned)dst >= (unsigned)N || (unsigned)t >= NREL ||
        (unsigned)src >= (unsigned)N) return;
    atomicAdd(&g_cnt[t * N + dst], 1);
}

__global__ void scan_blocksum_kernel(int n) {
    __shared__ int sdata[256];
    int b = blockIdx.x, t = threadIdx.x;
    int base = b * CHUNK;
    int sum = 0;
    for (int i = t; i < CHUNK; i += 256) {
        int idx = base + i;
        sum += (idx < n) ? g_cnt[idx] : 0;
    }
    sdata[t] = sum;
    __syncthreads();
    for (int s = 128; s > 0; s >>= 1) {
        if (t < s) sdata[t] += sdata[t + s];
        __syncthreads();
    }
    if (t == 0) g_blocksum[b] = sdata[0];
}

// parallel exclusive scan of chunk totals (nb <= 256)
__global__ void scan_offsets_kernel(int nb, int n) {
    __shared__ int s[256];
    int t = threadIdx.x;
    int v = (t < nb) ? g_blocksum[t] : 0;
    s[t] = v;
    __syncthreads();
    for (int off = 1; off < 256; off <<= 1) {
        int u = (t >= off) ? s[t - off] : 0;
        __syncthreads();
        s[t] += u;
        __syncthreads();
    }
    if (t < nb) g_blocksum[t] = s[t] - v;          // exclusive
    if (t == nb - 1) g_start[n] = s[t];            // total
}

__global__ void scan_chunk_kernel(int n) {
    __shared__ int sdata[256];
    int b = blockIdx.x, t = threadIdx.x;
    int base = b * CHUNK + t * 16;
    int local[16];
    int sum = 0;
#pragma unroll
    for (int i = 0; i < 16; i++) {
        int idx = base + i;
        int v = (idx < n) ? g_cnt[idx] : 0;
        local[i] = sum;
        sum += v;
    }
    sdata[t] = sum;
    __syncthreads();
    if (t == 0) {
        int acc = 0;
        for (int i = 0; i < 256; i++) { int v = sdata[i]; sdata[i] = acc; acc += v; }
    }
    __syncthreads();
    int off = g_blocksum[b] + sdata[t];
#pragma unroll
    for (int i = 0; i < 16; i++) {
        int idx = base + i;
        if (idx < n) {
            int v = off + local[i];
            g_start[idx] = v;
            g_pos[idx]   = v;
        }
    }
}

__global__ void scatter_edges_kernel(const int* __restrict__ ei,
                                     const int* __restrict__ et, int E, int N) {
    int e = blockIdx.x * blockDim.x + threadIdx.x;
    if (e >= E) return;
    int src = ei[e];
    int dst = ei[E + e];
    int t   = et[e];
    if ((unsigned)dst >= (unsigned)N || (unsigned)t >= NREL ||
        (unsigned)src >= (unsigned)N) return;
    int pos = atomicAdd(&g_pos[t * N + dst], 1);
    g_sorted[pos] = src;
}

// ---------------- aggregation: g_xw[seg] = mean over segment of x rows ----------------
// One warp per segment (= (rel,dst)); lane l owns float4 l. MLP-batched src prefetch.
__global__ void aggregate_all_kernel(const float* __restrict__ x, int N) {
    size_t gw = ((size_t)blockIdx.x * blockDim.x + threadIdx.x) >> 5;
    int lane = threadIdx.x & 31;
    if (gw >= (size_t)NREL * N) return;

    int b   = g_start[gw];
    int e2  = g_start[gw + 1];
    int cnt = e2 - b;
    const float4* x4 = (const float4*)x;

    float4 acc = make_float4(0.f, 0.f, 0.f, 0.f);
    int nc = cnt < 8 ? cnt : 8;
    int srcs[8];
#pragma unroll
    for (int j = 0; j < 8; j++) srcs[j] = (j < nc) ? g_sorted[b + j] : 0;
#pragma unroll
    for (int j = 0; j < 8; j++) {
        if (j < nc) {
            float4 v = x4[(size_t)srcs[j] * 32 + lane];
            acc.x += v.x; acc.y += v.y; acc.z += v.z; acc.w += v.w;
        }
    }
    for (int e = b + 8; e < e2; e++) {          // rare tail (P ~ 0.1%)
        int src = g_sorted[e];
        float4 v = x4[(size_t)src * 32 + lane];
        acc.x += v.x; acc.y += v.y; acc.z += v.z; acc.w += v.w;
    }
    float inv = (cnt > 0) ? 1.0f / (float)cnt : 0.0f;
    ((float4*)g_xw)[gw * 32 + lane] =
        make_float4(acc.x * inv, acc.y * inv, acc.z * inv, acc.w * inv);
}

// ---------------- tensor-core GEMM ----------------
// out[N,128] = [h_0..h_7 | x][N,1152] @ [W_0..W_7; root] + bias
// A source: kt<32 -> g_xw[(kt>>2)*N + row], kt>=32 -> x[row]
// bf16 2-term split: out = Ah*Bh + Ah*Bl + Al*Bh  (fp32 accum, mma.sync)
#define AS_STRIDE 40
#define BS_STRIDE 136

__device__ __forceinline__ uint32_t smem_u32(const void* p) {
    uint32_t a;
    asm("{ .reg .u64 t; cvta.to.shared.u64 t, %1; cvt.u32.u64 %0, t; }"
        : "=r"(a) : "l"(p));
    return a;
}

__device__ __forceinline__ void split2(float v0, float v1,
                                       uint32_t& hi, uint32_t& lo) {
    __nv_bfloat16 h0 = __float2bfloat16(v0);
    __nv_bfloat16 h1 = __float2bfloat16(v1);
    __nv_bfloat16 l0 = __float2bfloat16(v0 - __bfloat162float(h0));
    __nv_bfloat16 l1 = __float2bfloat16(v1 - __bfloat162float(h1));
    hi = (uint32_t)__bfloat16_as_ushort(h0) | ((uint32_t)__bfloat16_as_ushort(h1) << 16);
    lo = (uint32_t)__bfloat16_as_ushort(l0) | ((uint32_t)__bfloat16_as_ushort(l1) << 16);
}

#define LDSM_X4(r, addr)                                                        \
    asm volatile("ldmatrix.sync.aligned.m8n8.x4.shared.b16 {%0,%1,%2,%3},[%4];" \
                 : "=r"((r)[0]), "=r"((r)[1]), "=r"((r)[2]), "=r"((r)[3])        \
                 : "r"(addr))
#define LDSM_X4T(r, addr)                                                             \
    asm volatile("ldmatrix.sync.aligned.m8n8.x4.trans.shared.b16 {%0,%1,%2,%3},[%4];" \
                 : "=r"((r)[0]), "=r"((r)[1]), "=r"((r)[2]), "=r"((r)[3])              \
                 : "r"(addr))
#define MMA_BF16(d, a, b0, b1)                                              \
    asm volatile("mma.sync.aligned.m16n8k16.row.col.f32.bf16.bf16.f32 "     \
                 "{%0,%1,%2,%3},{%4,%5,%6,%7},{%8,%9},{%0,%1,%2,%3};"       \
                 : "+f"((d)[0]), "+f"((d)[1]), "+f"((d)[2]), "+f"((d)[3])    \
                 : "r"((a)[0]), "r"((a)[1]), "r"((a)[2]), "r"((a)[3]),       \
                   "r"(b0), "r"(b1))

__global__ __launch_bounds__(256, 1) void gemm_kernel(
    const float* __restrict__ x,
    const float* __restrict__ weight, const float* __restrict__ root,
    const float* __restrict__ bias, float* __restrict__ out, int N) {
    __shared__ __align__(16) unsigned short AsH[128 * AS_STRIDE];
    __shared__ __align__(16) unsigned short AsL[128 * AS_STRIDE];
    __shared__ __align__(16) unsigned short BsH[32 * BS_STRIDE];
    __shared__ __align__(16) unsigned short BsL[32 * BS_STRIDE];

    const int tid  = threadIdx.x;
    const int lane = tid & 31;
    const int wid  = tid >> 5;
    const int m0   = blockIdx.x * 128;
    const int wm   = (wid >> 1) * 32;
    const int wn   = (wid & 1) * 64;

    const float4* A4 = (const float4*)g_xw;   // [slot*N + node] * 32 f4
    const float4* x4 = (const float4*)x;

    float acc[2][8][4];
#pragma unroll
    for (int i = 0; i < 2; i++)
#pragma unroll
        for (int j = 0; j < 8; j++)
#pragma unroll
            for (int q = 0; q < 4; q++) acc[i][j][q] = 0.0f;

    for (int kt = 0; kt < 36; ++kt) {
        // stage A tile [128 rows x 32 k]
#pragma unroll
        for (int it = 0; it < 4; ++it) {
            int f   = tid + it * 256;
            int row = f >> 3;
            int q   = f & 7;
            int gr  = m0 + row;
            float4 v = make_float4(0.f, 0.f, 0.f, 0.f);
            if (gr < N) {
                if (kt < 32)
                    v = A4[((size_t)(kt >> 2) * N + gr) * 32 + (kt & 3) * 8 + q];
                else
                    v = x4[(size_t)gr * 32 + (kt - 32) * 8 + q];
            }
            uint32_t h0, l0, h1, l1;
            split2(v.x, v.y, h0, l0);
            split2(v.z, v.w, h1, l1);
            int o = row * AS_STRIDE + q * 4;
            *(uint32_t*)&AsH[o]     = h0;
            *(uint32_t*)&AsH[o + 2] = h1;
            *(uint32_t*)&AsL[o]     = l0;
            *(uint32_t*)&AsL[o + 2] = l1;
        }
        // stage B tile [32 k x 128 n]
        const float4* Bsrc = (kt < 32)
            ? (const float4*)(weight + (size_t)kt * 32 * 128)
            : (const float4*)(root + (size_t)(kt - 32) * 32 * 128);
#pragma unroll
        for (int it = 0; it < 4; ++it) {
            int f    = tid + it * 256;
            int krow = f >> 5;
            int n4   = f & 31;
            float4 w = Bsrc[f];
            uint32_t h0, l0, h1, l1;
            split2(w.x, w.y, h0, l0);
            split2(w.z, w.w, h1, l1);
            int o = krow * BS_STRIDE + n4 * 4;
            *(uint32_t*)&BsH[o]     = h0;
            *(uint32_t*)&BsH[o + 2] = h1;
            *(uint32_t*)&BsL[o]     = l0;
            *(uint32_t*)&BsL[o + 2] = l1;
        }
        __syncthreads();

#pragma unroll
        for (int kk = 0; kk < 32; kk += 16) {
            uint32_t ah[2][4], al[2][4];
#pragma unroll
            for (int mi = 0; mi < 2; mi++) {
                int r = wm + mi * 16 + (lane & 15);
                int c = kk + (lane >> 4) * 8;
                LDSM_X4(ah[mi], smem_u32(&AsH[r * AS_STRIDE + c]));
                LDSM_X4(al[mi], smem_u32(&AsL[r * AS_STRIDE + c]));
            }
            uint32_t bh[4][4], bl[4][4];
#pragma unroll
            for (int ni = 0; ni < 4; ni++) {
                int r = kk + (lane & 15);
                int c = wn + ni * 16 + (lane >> 4) * 8;
                LDSM_X4T(bh[ni], smem_u32(&BsH[r * BS_STRIDE + c]));
                LDSM_X4T(bl[ni], smem_u32(&BsL[r * BS_STRIDE + c]));
            }
#pragma unroll
            for (int mi = 0; mi < 2; mi++)
#pragma unroll
                for (int ni = 0; ni < 4; ni++) {
                    MMA_BF16(acc[mi][ni * 2],     ah[mi], bh[ni][0], bh[ni][1]);
                    MMA_BF16(acc[mi][ni * 2],     ah[mi], bl[ni][0], bl[ni][1]);
                    MMA_BF16(acc[mi][ni * 2],     al[mi], bh[ni][0], bh[ni][1]);
                    MMA_BF16(acc[mi][ni * 2 + 1], ah[mi], bh[ni][2], bh[ni][3]);
                    MMA_BF16(acc[mi][ni * 2 + 1], ah[mi], bl[ni][2], bl[ni][3]);
                    MMA_BF16(acc[mi][ni * 2 + 1], al[mi], bh[ni][2], bh[ni][3]);
                }
        }
        __syncthreads();
    }

    // epilogue
    int r0 = lane >> 2;
    int c0 = (lane & 3) * 2;
#pragma unroll
    for (int mi = 0; mi < 2; mi++)
#pragma unroll
        for (int n8 = 0; n8 < 8; n8++) {
            int gn = wn + n8 * 8 + c0;
            float b0 = bias[gn], b1 = bias[gn + 1];
            int gm = m0 + wm + mi * 16 + r0;
            if (gm < N) {
                float2* p = (float2*)(out + (size_t)gm * CH + gn);
                *p = make_float2(acc[mi][n8][0] + b0, acc[mi][n8][1] + b1);
            }
            if (gm + 8 < N) {
                float2* p = (float2*)(out + (size_t)(gm + 8) * CH + gn);
                *p = make_float2(acc[mi][n8][2] + b0, acc[mi][n8][3] + b1);
            }
        }
}

// ---------------- launch ----------------
extern "C" void kernel_launch(void* const* d_in, const int* in_sizes, int n_in,
                              void* d_out, int out_size) {
    const float* x      = (const float*)d_in[0];
    const int*   ei     = (const int*)d_in[1];    // int32 (JAX x64 off)
    const int*   et     = (const int*)d_in[2];
    const float* weight = (const float*)d_in[3];
    const float* root   = (const float*)d_in[4];
    const float* bias   = (const float*)d_in[5];
    float*       out    = (float*)d_out;

    int N  = in_sizes[0] / CH;       // 100000
    int E  = in_sizes[2];            // 1600000
    int RN = NREL * N;
    int nb = (RN + CHUNK - 1) / CHUNK;
    int gemm_blocks = (N + 127) / 128;
    int agg_blocks  = (int)(((size_t)RN * 32 + 255) / 256);

    // CSR build
    zero_cnt_kernel<<<(RN + 255) / 256, 256>>>(RN);
    hist_kernel<<<(E + 255) / 256, 256>>>(ei, et, E, N);
    scan_blocksum_kernel<<<nb, 256>>>(RN);
    scan_offsets_kernel<<<1, 256>>>(nb, RN);
    scan_chunk_kernel<<<nb, 256>>>(RN);
    scatter_edges_kernel<<<(E + 255) / 256, 256>>>(ei, et, E, N);

    // aggregation (8 relation means, MLP-batched) -> g_xw [8,N,128]
    aggregate_all_kernel<<<agg_blocks, 256>>>(x, N);

    // tensor GEMM: out = [h_0..h_7 | x] @ [W_0..W_7; root] + bias
    gemm_kernel<<<gemm_blocks, 256>>>(x, weight, root, bias, out, N);
}